// round 15
// baseline (speedup 1.0000x reference)
#include <cuda_runtime.h>
#include <cuda_bf16.h>
#include <cuda_fp16.h>
#include <cstdint>

#define NN 100000
#define EE 1600000
#define PP 100000
#define D  128
#define NB 391   // ceil(NN/256)

// ---- smem layout (bytes) ----
#define ROWP     272            // 136 bf16 per row (128 used + pad)
#define AH_OFF   0              // A hi : 64 x ROWP
#define AL_OFF   17408
#define WH_OFF   34816          // W hi : 128 x ROWP
#define WL_OFF   69632          // contiguous after WH
#define SIDX_OFF 104448
#define DIDX_OFF 104704
#define PART_OFF 104960         // 2 x 64 floats
#define SMEM_TOT 105472

#define WTILE_B  34816          // 128 * ROWP

// ================= scratch (device globals; no allocation) =================
__device__ __align__(128) __half g_h0   [(size_t)NN * D];
__device__ __align__(128) __half g_h1   [(size_t)NN * D];
__device__ __align__(128) __half g_h2   [(size_t)NN * D];
__device__ __align__(128) float  g_rep  [(size_t)NN * D];
__device__ __align__(128) __half g_rep16[(size_t)NN * D];
__device__ __align__(16)  char   g_wt   [4][2][WTILE_B];  // w1,w2,pw1,pw2 hi/lo
__device__ int   g_cnt_in [NN];
__device__ int   g_cnt_out[NN];
__device__ float g_rs_in  [NN];
__device__ float g_rs_out [NN];
__device__ float g_sq_out [NN];
__device__ int   g_row_ptr[NN + 1];
__device__ int   g_cursor [NN];
__device__ int   g_col    [EE];
__device__ int   g_bsum   [NB];

// ================= graph structure ==========================================
__global__ void zero_cnt_kernel() {
    int v = blockIdx.x * blockDim.x + threadIdx.x;
    if (v < NN) { g_cnt_in[v] = 0; g_cnt_out[v] = 0; }
}

__global__ void count_deg_kernel(const int2* __restrict__ src2, const int2* __restrict__ dst2) {
    int i = blockIdx.x * blockDim.x + threadIdx.x;
    if (i < EE / 2) {
        int2 s = src2[i];
        int2 d = dst2[i];
        atomicAdd(&g_cnt_out[s.x], 1);
        atomicAdd(&g_cnt_out[s.y], 1);
        atomicAdd(&g_cnt_in [d.x], 1);
        atomicAdd(&g_cnt_in [d.y], 1);
    }
}

__global__ void scanA_kernel() {
    __shared__ int sh[256];
    int i = blockIdx.x * 256 + threadIdx.x;
    int v = (i < NN) ? g_cnt_in[i] : 0;
    sh[threadIdx.x] = v;
    __syncthreads();
    for (int off = 128; off > 0; off >>= 1) {
        if (threadIdx.x < off) sh[threadIdx.x] += sh[threadIdx.x + off];
        __syncthreads();
    }
    if (threadIdx.x == 0) g_bsum[blockIdx.x] = sh[0];
}

__global__ void scanBC_kernel() {
    __shared__ int sh[256];
    __shared__ int s_pref;
    int b = blockIdx.x;
    int i = b * 256 + threadIdx.x;

    int part = 0;
    for (int j = threadIdx.x; j < b; j += 256) part += g_bsum[j];
    sh[threadIdx.x] = part;
    __syncthreads();
    for (int off = 128; off > 0; off >>= 1) {
        if (threadIdx.x < off) sh[threadIdx.x] += sh[threadIdx.x + off];
        __syncthreads();
    }
    if (threadIdx.x == 0) s_pref = sh[0];
    __syncthreads();
    int boff = s_pref;
    __syncthreads();

    int v = (i < NN) ? g_cnt_in[i] : 0;
    sh[threadIdx.x] = v;
    __syncthreads();
    for (int off = 1; off < 256; off <<= 1) {
        int x = (threadIdx.x >= off) ? sh[threadIdx.x - off] : 0;
        __syncthreads();
        sh[threadIdx.x] += x;
        __syncthreads();
    }
    if (i < NN) {
        int incl = boff + sh[threadIdx.x];
        g_row_ptr[i + 1] = incl;
        g_cursor[i] = incl - v;
        int ci = v; if (ci < 1) ci = 1;
        int co = g_cnt_out[i]; if (co < 1) co = 1;
        g_rs_in [i] = rsqrtf((float)ci);
        g_rs_out[i] = rsqrtf((float)co);
        g_sq_out[i] = sqrtf((float)co);
        if (i == 0) g_row_ptr[0] = 0;
    }
}

__global__ void scatter_edges_kernel(const int2* __restrict__ src2, const int2* __restrict__ dst2) {
    int i = blockIdx.x * blockDim.x + threadIdx.x;
    if (i < EE / 2) {
        int2 s = src2[i];
        int2 d = dst2[i];
        int p0 = atomicAdd(&g_cursor[d.x], 1);
        g_col[p0] = s.x;
        int p1 = atomicAdd(&g_cursor[d.y], 1);
        g_col[p1] = s.y;
    }
}

// ================= bf16 split helpers =======================================
__device__ __forceinline__ void split_bf(float v, unsigned& h, unsigned& l) {
    __nv_bfloat16 hb = __float2bfloat16(v);
    float r = v - __bfloat162float(hb);
    __nv_bfloat16 lb = __float2bfloat16(r);
    h = (unsigned)__bfloat16_as_ushort(hb);
    l = (unsigned)__bfloat16_as_ushort(lb);
}
__device__ __forceinline__ void split4(float4 v, uint2& hi, uint2& lo) {
    unsigned h0, h1, h2, h3, l0, l1, l2, l3;
    split_bf(v.x, h0, l0);
    split_bf(v.y, h1, l1);
    split_bf(v.z, h2, l2);
    split_bf(v.w, h3, l3);
    hi.x = h0 | (h1 << 16); hi.y = h2 | (h3 << 16);
    lo.x = l0 | (l1 << 16); lo.y = l2 | (l3 << 16);
}

__global__ void prep_w_kernel(const float* __restrict__ w1, const float* __restrict__ w2,
                              const float* __restrict__ pw1, const float* __restrict__ pw2) {
    const float* W = (blockIdx.x == 0) ? w1 : (blockIdx.x == 1) ? w2
                   : (blockIdx.x == 2) ? pw1 : pw2;
    char* hiB = &g_wt[blockIdx.x][0][0];
    char* loB = &g_wt[blockIdx.x][1][0];
    int tid = threadIdx.x;
#pragma unroll
    for (int it = 0; it < 16; it++) {
        int idx4 = tid + it * 256;
        int k  = idx4 >> 5;
        int c4 = idx4 & 31;
        float4 v = *(const float4*)(W + (size_t)k * 128 + c4 * 4);
        uint2 hi, lo;
        split4(v, hi, lo);
        *(uint2*)(hiB + k * ROWP + c4 * 8) = hi;
        *(uint2*)(loB + k * ROWP + c4 * 8) = lo;
    }
}

// ================= graph conv (fp16, dual-node-per-warp) ====================
__device__ __forceinline__ void acc_edge_s(float4& acc, const __half* __restrict__ hin,
                                           int s, int lane) {
    float m = g_rs_out[s];
    uint2 rv = *(const uint2*)(hin + (size_t)s * D + lane * 4);
    float2 f0 = __half22float2(*reinterpret_cast<__half2*>(&rv.x));
    float2 f1 = __half22float2(*reinterpret_cast<__half2*>(&rv.y));
    acc.x = fmaf(m, f0.x, acc.x);
    acc.y = fmaf(m, f0.y, acc.y);
    acc.z = fmaf(m, f1.x, acc.z);
    acc.w = fmaf(m, f1.y, acc.w);
}
__device__ __forceinline__ void acc_edge_p(float4& acc, const __half* __restrict__ hin,
                                           int s, int lane) {
    uint2 rv = *(const uint2*)(hin + (size_t)s * D + lane * 4);
    float2 f0 = __half22float2(*reinterpret_cast<__half2*>(&rv.x));
    float2 f1 = __half22float2(*reinterpret_cast<__half2*>(&rv.y));
    acc.x += f0.x; acc.y += f0.y; acc.z += f1.x; acc.w += f1.y;
}

// tail: finish one row from e to end
template <int SCALED>
__device__ __forceinline__ void gather_tail(float4& acc, const __half* __restrict__ hin,
                                            int e, int end, int lane) {
    for (; e + 4 <= end; e += 4) {
        int s[4];
#pragma unroll
        for (int j = 0; j < 4; j++) s[j] = g_col[e + j];
#pragma unroll
        for (int j = 0; j < 4; j++) {
            if (SCALED) acc_edge_s(acc, hin, s[j], lane);
            else        acc_edge_p(acc, hin, s[j], lane);
        }
    }
    for (; e < end; e++) {
        if (SCALED) acc_edge_s(acc, hin, g_col[e], lane);
        else        acc_edge_p(acc, hin, g_col[e], lane);
    }
}

// gather two rows (w0, w1) with interleaved 4-wide chunks
template <int SCALED>
__device__ __forceinline__ void gather_two(float4& acc0, float4& acc1,
                                           const __half* __restrict__ hin,
                                           int w0, int w1, int lane) {
    acc0 = make_float4(0.f, 0.f, 0.f, 0.f);
    acc1 = make_float4(0.f, 0.f, 0.f, 0.f);
    int e0 = g_row_ptr[w0], end0 = g_row_ptr[w0 + 1];
    int e1 = g_row_ptr[w1], end1 = g_row_ptr[w1 + 1];
    while (e0 + 4 <= end0 && e1 + 4 <= end1) {
        int s0[4], s1[4];
#pragma unroll
        for (int j = 0; j < 4; j++) s0[j] = g_col[e0 + j];
#pragma unroll
        for (int j = 0; j < 4; j++) s1[j] = g_col[e1 + j];
#pragma unroll
        for (int j = 0; j < 4; j++) {
            if (SCALED) { acc_edge_s(acc0, hin, s0[j], lane); acc_edge_s(acc1, hin, s1[j], lane); }
            else        { acc_edge_p(acc0, hin, s0[j], lane); acc_edge_p(acc1, hin, s1[j], lane); }
        }
        e0 += 4; e1 += 4;
    }
    gather_tail<SCALED>(acc0, hin, e0, end0, lane);
    gather_tail<SCALED>(acc1, hin, e1, end1, lane);
}

__device__ __forceinline__ void write_mid(__half* __restrict__ hout, int w, int lane,
                                          float4 acc) {
    float sc = g_rs_in[w] * g_rs_out[w];
    __half2 o0 = __floats2half2_rn(sc * acc.x, sc * acc.y);
    __half2 o1 = __floats2half2_rn(sc * acc.z, sc * acc.w);
    uint2 ov;
    ov.x = *reinterpret_cast<uint32_t*>(&o0);
    ov.y = *reinterpret_cast<uint32_t*>(&o1);
    *(uint2*)(hout + (size_t)w * D + lane * 4) = ov;
}

// warp handles nodes 2k and 2k+1 (NN is even)
template <int SCALED>
__global__ void aggregate_mid_kernel(const __half* __restrict__ hin,
                                     __half* __restrict__ hout) {
    int wp   = (blockIdx.x * blockDim.x + threadIdx.x) >> 5;
    int lane = threadIdx.x & 31;
    int w0 = wp * 2;
    if (w0 >= NN) return;
    int w1 = w0 + 1;
    float4 acc0, acc1;
    gather_two<SCALED>(acc0, acc1, hin, w0, w1, lane);
    write_mid(hout, w0, lane, acc0);
    write_mid(hout, w1, lane, acc1);
}

__device__ __forceinline__ void write_last(const __half* __restrict__ h2p,
                                           const __half* __restrict__ h1p,
                                           const float* __restrict__ rep,
                                           __half* __restrict__ rep16,
                                           const float* __restrict__ gamma,
                                           int w, int lane, float4 acc) {
    float rin = g_rs_in[w];
    float sqo = g_sq_out[w];
    float c1 = gamma[1] * sqo, c2 = gamma[2] * sqo, c3 = gamma[3] * rin;
    size_t off = (size_t)w * D + lane * 4;

    uint2 r1 = *(const uint2*)(h1p + off);
    uint2 r2 = *(const uint2*)(h2p + off);
    float2 a1 = __half22float2(*reinterpret_cast<__half2*>(&r1.x));
    float2 b1v = __half22float2(*reinterpret_cast<__half2*>(&r1.y));
    float2 a2 = __half22float2(*reinterpret_cast<__half2*>(&r2.x));
    float2 b2v = __half22float2(*reinterpret_cast<__half2*>(&r2.y));

    float4 rp = __ldcs((const float4*)(rep + off));
    rp.x += c1 * a1.x + c2 * a2.x + c3 * acc.x;
    rp.y += c1 * a1.y + c2 * a2.y + c3 * acc.y;
    rp.z += c1 * b1v.x + c2 * b2v.x + c3 * acc.z;
    rp.w += c1 * b1v.y + c2 * b2v.y + c3 * acc.w;

    __half2 o0 = __floats2half2_rn(rp.x, rp.y);
    __half2 o1 = __floats2half2_rn(rp.z, rp.w);
    uint2 ov;
    ov.x = *reinterpret_cast<uint32_t*>(&o0);
    ov.y = *reinterpret_cast<uint32_t*>(&o1);
    *(uint2*)(rep16 + off) = ov;
}

__global__ void aggregate_last_kernel(const __half* __restrict__ h2p,
                                      const __half* __restrict__ h1p,
                                      const float* __restrict__ gamma,
                                      const float* __restrict__ rep,
                                      __half* __restrict__ rep16) {
    int wp   = (blockIdx.x * blockDim.x + threadIdx.x) >> 5;
    int lane = threadIdx.x & 31;
    int w0 = wp * 2;
    if (w0 >= NN) return;
    int w1 = w0 + 1;
    float4 acc0, acc1;
    gather_two<0>(acc0, acc1, h2p, w0, w1, lane);
    write_last(h2p, h1p, rep, rep16, gamma, w0, lane, acc0);
    write_last(h2p, h1p, rep, rep16, gamma, w1, lane, acc1);
}

// ================= mma.sync plumbing (virtual-arch-safe PTX) ================
__device__ __forceinline__ uint32_t smem_u32(const void* p) {
    uint32_t a;
    asm("{ .reg .u64 t; cvta.to.shared.u64 t, %1; cvt.u32.u64 %0, t; }" : "=r"(a) : "l"(p));
    return a;
}

#define LDSM_X4(R, A)                                                        \
    asm volatile("ldmatrix.sync.aligned.m8n8.x4.shared.b16 {%0,%1,%2,%3}, [%4];" \
        : "=r"((R)[0]), "=r"((R)[1]), "=r"((R)[2]), "=r"((R)[3]) : "r"(A))

#define LDSM_X4T(R, A)                                                       \
    asm volatile("ldmatrix.sync.aligned.m8n8.x4.trans.shared.b16 {%0,%1,%2,%3}, [%4];" \
        : "=r"((R)[0]), "=r"((R)[1]), "=r"((R)[2]), "=r"((R)[3]) : "r"(A))

#define MMA16816(C, AR, B0, B1)                                              \
    asm volatile("mma.sync.aligned.m16n8k16.row.col.f32.bf16.bf16.f32 "      \
        "{%0,%1,%2,%3}, {%4,%5,%6,%7}, {%8,%9}, {%0,%1,%2,%3};"              \
        : "+f"((C)[0]), "+f"((C)[1]), "+f"((C)[2]), "+f"((C)[3])             \
        : "r"((AR)[0]), "r"((AR)[1]), "r"((AR)[2]), "r"((AR)[3]),            \
          "r"(B0), "r"(B1))

__device__ __forceinline__ void load_W(char* sm, int widx, int tid) {
    const uint4* src = (const uint4*)&g_wt[widx][0][0];
    uint4* dst = (uint4*)(sm + WH_OFF);
#pragma unroll
    for (int i = 0; i < 17; i++)
        dst[tid + i * 256] = src[tid + i * 256];
}

__device__ __forceinline__ void gemm_core(uint32_t sb, float acc[8][4],
                                          int wm, int wn, int lane) {
#pragma unroll
    for (int i = 0; i < 8; i++)
#pragma unroll
        for (int j = 0; j < 4; j++) acc[i][j] = 0.f;

    const uint32_t a_addr = sb + AH_OFF + (uint32_t)(wm + (lane & 15)) * ROWP
                            + ((lane >> 4) << 4);
    const uint32_t b_row  = (uint32_t)(lane & 15) * ROWP;
    const uint32_t b_col  = (uint32_t)wn * 2 + ((lane >> 4) << 4);

#pragma unroll
    for (int ks = 0; ks < 8; ks++) {
        uint32_t ah[4], al[4];
        LDSM_X4(ah, a_addr + ks * 32);
        LDSM_X4(al, a_addr + ks * 32 + (AL_OFF - AH_OFF));
        uint32_t bbase = sb + WH_OFF + (uint32_t)(ks * 16) * ROWP + b_row + b_col;
#pragma unroll
        for (int g = 0; g < 4; g++) {
            uint32_t bh[4], bl[4];
            uint32_t ba = bbase + g * 32;
            LDSM_X4T(bh, ba);
            LDSM_X4T(bl, ba + (WL_OFF - WH_OFF));
            MMA16816(acc[2 * g],     ah, bh[0], bh[1]);
            MMA16816(acc[2 * g + 1], ah, bh[2], bh[3]);
            MMA16816(acc[2 * g],     ah, bl[0], bl[1]);
            MMA16816(acc[2 * g + 1], ah, bl[2], bl[3]);
            MMA16816(acc[2 * g],     al, bh[0], bh[1]);
            MMA16816(acc[2 * g + 1], al, bh[2], bh[3]);
        }
    }
}

__device__ __forceinline__ void epi_to_A(char* sm, float acc[8][4],
                                         const float* __restrict__ bias,
                                         int wm, int wn, int lane) {
    int r0 = wm + (lane >> 2);
    int r1 = r0 + 8;
#pragma unroll
    for (int nt = 0; nt < 8; nt++) {
        int c = wn + nt * 8 + 2 * (lane & 3);
        float2 bv = *(const float2*)(bias + c);
        float v0 = fmaxf(acc[nt][0] + bv.x, 0.f);
        float v1 = fmaxf(acc[nt][1] + bv.y, 0.f);
        float v2 = fmaxf(acc[nt][2] + bv.x, 0.f);
        float v3 = fmaxf(acc[nt][3] + bv.y, 0.f);
        unsigned h0, h1, h2, h3, l0, l1, l2, l3;
        split_bf(v0, h0, l0); split_bf(v1, h1, l1);
        split_bf(v2, h2, l2); split_bf(v3, h3, l3);
        *(uint32_t*)(sm + AH_OFF + r0 * ROWP + c * 2) = h0 | (h1 << 16);
        *(uint32_t*)(sm + AL_OFF + r0 * ROWP + c * 2) = l0 | (l1 << 16);
        *(uint32_t*)(sm + AH_OFF + r1 * ROWP + c * 2) = h2 | (h3 << 16);
        *(uint32_t*)(sm + AL_OFF + r1 * ROWP + c * 2) = l2 | (l3 << 16);
    }
}

// ================= fused node MLP (mma.sync) ================================
__global__ __launch_bounds__(256) void mlp_mma_kernel(
        const float* __restrict__ x,
        const float* __restrict__ b1, const float* __restrict__ b2,
        const float* __restrict__ gam,
        __half* __restrict__ hs16, float* __restrict__ rep) {
    extern __shared__ char sm[];
    const uint32_t sb = smem_u32(sm);
    const int tid  = threadIdx.x;
    const int wid  = tid >> 5;
    const int lane = tid & 31;
    const int wm   = (wid & 3) * 16;
    const int wn   = (wid >> 2) * 64;
    const int blockRow = blockIdx.x * 64;

#pragma unroll
    for (int it = 0; it < 8; it++) {
        int idx4 = tid + it * 256;
        int r  = idx4 >> 5;
        int c4 = idx4 & 31;
        float4 v = make_float4(0.f, 0.f, 0.f, 0.f);
        if (blockRow + r < NN)
            v = *(const float4*)(x + (size_t)(blockRow + r) * D + c4 * 4);
        uint2 hi, lo;
        split4(v, hi, lo);
        *(uint2*)(sm + AH_OFF + r * ROWP + c4 * 8) = hi;
        *(uint2*)(sm + AL_OFF + r * ROWP + c4 * 8) = lo;
    }
    load_W(sm, 0, tid);
    __syncthreads();

    float acc[8][4];
    gemm_core(sb, acc, wm, wn, lane);
    __syncthreads();

    epi_to_A(sm, acc, b1, wm, wn, lane);
    load_W(sm, 1, tid);
    __syncthreads();

    gemm_core(sb, acc, wm, wn, lane);

    {
        float g0 = gam[0];
        int r0 = blockRow + wm + (lane >> 2);
        int r1 = r0 + 8;
        bool ok0 = (r0 < NN), ok1 = (r1 < NN);
#pragma unroll
        for (int nt = 0; nt < 8; nt++) {
            int c = wn + nt * 8 + 2 * (lane & 3);
            float2 bv = *(const float2*)(b2 + c);
            if (ok0) {
                float h0 = acc[nt][0] + bv.x;
                float h1 = acc[nt][1] + bv.y;
                __stcs((float2*)(rep + (size_t)r0 * D + c), make_float2(g0 * h0, g0 * h1));
                __half2 hh = __floats2half2_rn(h0, h1);
                *(uint32_t*)(hs16 + (size_t)r0 * D + c) = *reinterpret_cast<uint32_t*>(&hh);
            }
            if (ok1) {
                float h2 = acc[nt][2] + bv.x;
                float h3 = acc[nt][3] + bv.y;
                __stcs((float2*)(rep + (size_t)r1 * D + c), make_float2(g0 * h2, g0 * h3));
                __half2 hh = __floats2half2_rn(h2, h3);
                *(uint32_t*)(hs16 + (size_t)r1 * D + c) = *reinterpret_cast<uint32_t*>(&hh);
            }
        }
    }
}

// ================= fused predictor (mma.sync, fp16 rep) =====================
__global__ __launch_bounds__(256) void pred_mma_kernel(
        const int* __restrict__ ps, const int* __restrict__ pd,
        const int* __restrict__ ns, const int* __restrict__ nd,
        const float* __restrict__ b1, const float* __restrict__ b2,
        const float* __restrict__ w3, const float* __restrict__ b3,
        const __half* __restrict__ rep16, float* __restrict__ out) {
    extern __shared__ char sm[];
    const uint32_t sb = smem_u32(sm);
    const int tid  = threadIdx.x;
    const int wid  = tid >> 5;
    const int lane = tid & 31;
    const int wm   = (wid & 3) * 16;
    const int wn   = (wid >> 2) * 64;
    const int base = blockIdx.x * 64;

    int* sidx = (int*)(sm + SIDX_OFF);
    int* didx = (int*)(sm + DIDX_OFF);
    float* part = (float*)(sm + PART_OFF);

    if (tid < 64) {
        int w = base + tid;
        int s, d;
        if (w < PP) { s = ps[w]; d = pd[w]; }
        else        { s = ns[w - PP]; d = nd[w - PP]; }
        sidx[tid] = s; didx[tid] = d;
    }
    __syncthreads();

#pragma unroll
    for (int it = 0; it < 8; it++) {
        int idx4 = tid + it * 256;
        int r  = idx4 >> 5;
        int c4 = idx4 & 31;
        uint2 ra = *(const uint2*)(rep16 + (size_t)sidx[r] * D + c4 * 4);
        uint2 rb = *(const uint2*)(rep16 + (size_t)didx[r] * D + c4 * 4);
        float2 a0 = __half22float2(*reinterpret_cast<__half2*>(&ra.x));
        float2 a1 = __half22float2(*reinterpret_cast<__half2*>(&ra.y));
        float2 b0 = __half22float2(*reinterpret_cast<__half2*>(&rb.x));
        float2 b1h = __half22float2(*reinterpret_cast<__half2*>(&rb.y));
        float4 v;
        v.x = a0.x * b0.x; v.y = a0.y * b0.y;
        v.z = a1.x * b1h.x; v.w = a1.y * b1h.y;
        uint2 hi, lo;
        split4(v, hi, lo);
        *(uint2*)(sm + AH_OFF + r * ROWP + c4 * 8) = hi;
        *(uint2*)(sm + AL_OFF + r * ROWP + c4 * 8) = lo;
    }
    load_W(sm, 2, tid);
    __syncthreads();

    float acc[8][4];
    gemm_core(sb, acc, wm, wn, lane);
    __syncthreads();

    epi_to_A(sm, acc, b1, wm, wn, lane);
    load_W(sm, 3, tid);
    __syncthreads();

    gemm_core(sb, acc, wm, wn, lane);

    {
        float p0 = 0.f, p1 = 0.f;
#pragma unroll
        for (int nt = 0; nt < 8; nt++) {
            int c = wn + nt * 8 + 2 * (lane & 3);
            float2 bv = *(const float2*)(b2 + c);
            float2 wv = *(const float2*)(w3 + c);
            p0 += fmaxf(acc[nt][0] + bv.x, 0.f) * wv.x
                + fmaxf(acc[nt][1] + bv.y, 0.f) * wv.y;
            p1 += fmaxf(acc[nt][2] + bv.x, 0.f) * wv.x
                + fmaxf(acc[nt][3] + bv.y, 0.f) * wv.y;
        }
        p0 += __shfl_xor_sync(0xFFFFFFFFu, p0, 1);
        p0 += __shfl_xor_sync(0xFFFFFFFFu, p0, 2);
        p1 += __shfl_xor_sync(0xFFFFFFFFu, p1, 1);
        p1 += __shfl_xor_sync(0xFFFFFFFFu, p1, 2);
        if ((lane & 3) == 0) {
            int g = (wn >> 6);
            int rl = wm + (lane >> 2);
            part[g * 64 + rl]     = p0;
            part[g * 64 + rl + 8] = p1;
        }
    }
    __syncthreads();
    if (tid < 64) {
        out[base + tid] = part[tid] + part[64 + tid] + b3[0];
    }
}

// ================= launch ===================================================
extern "C" void kernel_launch(void* const* d_in, const int* in_sizes, int n_in,
                              void* d_out, int out_size) {
    const float* x   = (const float*)d_in[0];
    const float* w1  = (const float*)d_in[1];
    const float* b1  = (const float*)d_in[2];
    const float* w2  = (const float*)d_in[3];
    const float* b2  = (const float*)d_in[4];
    const float* gam = (const float*)d_in[5];
    const float* pw1 = (const float*)d_in[6];
    const float* pb1 = (const float*)d_in[7];
    const float* pw2 = (const float*)d_in[8];
    const float* pb2 = (const float*)d_in[9];
    const float* pw3 = (const float*)d_in[10];
    const float* pb3 = (const float*)d_in[11];
    const int* src = (const int*)d_in[12];
    const int* dst = (const int*)d_in[13];
    const int* ps  = (const int*)d_in[14];
    const int* pd  = (const int*)d_in[15];
    const int* ns  = (const int*)d_in[16];
    const int* nd  = (const int*)d_in[17];
    float* out = (float*)d_out;

    void *v0, *v1, *v2, *vrep, *vrep16;
    cudaGetSymbolAddress(&v0,     g_h0);
    cudaGetSymbolAddress(&v1,     g_h1);
    cudaGetSymbolAddress(&v2,     g_h2);
    cudaGetSymbolAddress(&vrep,   g_rep);
    cudaGetSymbolAddress(&vrep16, g_rep16);
    __half* h0 = (__half*)v0;
    __half* h1 = (__half*)v1;
    __half* h2 = (__half*)v2;
    float*  rep   = (float*)vrep;
    __half* rep16 = (__half*)vrep16;

    cudaFuncSetAttribute(mlp_mma_kernel,  cudaFuncAttributeMaxDynamicSharedMemorySize, SMEM_TOT);
    cudaFuncSetAttribute(pred_mma_kernel, cudaFuncAttributeMaxDynamicSharedMemorySize, SMEM_TOT);

    // ---- fork: CSR setup on side stream, weights+MLP on origin stream ----
    cudaStream_t s1 = 0;
    cudaEvent_t eF = 0, eJ = 0;
    bool fork_ok =
        cudaStreamCreateWithFlags(&s1, cudaStreamNonBlocking) == cudaSuccess &&
        cudaEventCreateWithFlags(&eF, cudaEventDisableTiming) == cudaSuccess &&
        cudaEventCreateWithFlags(&eJ, cudaEventDisableTiming) == cudaSuccess;
    if (fork_ok)
        fork_ok = (cudaEventRecord(eF, 0) == cudaSuccess) &&
                  (cudaStreamWaitEvent(s1, eF, 0) == cudaSuccess);
    cudaStream_t ss = fork_ok ? s1 : (cudaStream_t)0;

    const int TB = 256;
    zero_cnt_kernel<<<NB, TB, 0, ss>>>();
    count_deg_kernel<<<(EE / 2 + TB - 1) / TB, TB, 0, ss>>>((const int2*)src, (const int2*)dst);
    scanA_kernel<<<NB, TB, 0, ss>>>();
    scanBC_kernel<<<NB, TB, 0, ss>>>();
    scatter_edges_kernel<<<(EE / 2 + TB - 1) / TB, TB, 0, ss>>>((const int2*)src, (const int2*)dst);
    if (fork_ok) cudaEventRecord(eJ, s1);

    prep_w_kernel<<<4, 256>>>(w1, w2, pw1, pw2);
    mlp_mma_kernel<<<(NN + 63) / 64, TB, SMEM_TOT>>>(x, b1, b2, gam, h0, rep);

    if (fork_ok) cudaStreamWaitEvent((cudaStream_t)0, eJ, 0);

    const int NWP = (NN / 2) * 32;   // dual-node warps
    aggregate_mid_kernel<1><<<(NWP + TB - 1) / TB, TB>>>(h0, h1);
    aggregate_mid_kernel<0><<<(NWP + TB - 1) / TB, TB>>>(h1, h2);
    aggregate_last_kernel<<<(NWP + TB - 1) / TB, TB>>>(h2, h1, gam, rep, rep16);

    pred_mma_kernel<<<(2 * PP) / 64, TB, SMEM_TOT>>>(
        ps, pd, ns, nd, pb1, pb2, pw3, pb3, rep16, out);
}

// round 16
// speedup vs baseline: 1.0352x; 1.0352x over previous
#include <cuda_runtime.h>
#include <cuda_bf16.h>
#include <cuda_fp16.h>
#include <cstdint>

#define NN 100000
#define EE 1600000
#define PP 100000
#define D  128
#define NB 391   // ceil(NN/256)

// ---- smem layout (bytes) ----
#define ROWP     272            // 136 bf16 per row (128 used + pad)
#define AH_OFF   0              // A hi : 64 x ROWP
#define AL_OFF   17408
#define WH_OFF   34816          // W hi : 128 x ROWP
#define WL_OFF   69632          // contiguous after WH
#define SIDX_OFF 104448
#define DIDX_OFF 104704
#define PART_OFF 104960         // 2 x 64 floats
#define SMEM_TOT 105472

#define WTILE_B  34816          // 128 * ROWP

// ================= scratch (device globals; no allocation) =================
__device__ __align__(128) __half g_h0   [(size_t)NN * D];
__device__ __align__(128) __half g_h1   [(size_t)NN * D];
__device__ __align__(128) __half g_h2   [(size_t)NN * D];
__device__ __align__(128) float  g_rep  [(size_t)NN * D];
__device__ __align__(128) __half g_rep16[(size_t)NN * D];
__device__ __align__(16)  char   g_wt   [4][2][WTILE_B];  // w1,w2,pw1,pw2 hi/lo
__device__ int   g_cnt_in [NN];
__device__ int   g_cnt_out[NN];
__device__ float g_rs_in  [NN];
__device__ float g_rs_out [NN];
__device__ float g_sq_out [NN];
__device__ int   g_row_ptr[NN + 1];
__device__ int   g_cursor [NN];
__device__ int   g_col    [EE];
__device__ int   g_bsum   [NB];

// ================= graph structure ==========================================
__global__ void zero_cnt_kernel() {
    int v = blockIdx.x * blockDim.x + threadIdx.x;
    if (v < NN) { g_cnt_in[v] = 0; g_cnt_out[v] = 0; }
}

__global__ void count_deg_kernel(const int* __restrict__ src, const int* __restrict__ dst) {
    int e = blockIdx.x * blockDim.x + threadIdx.x;
    if (e < EE) {
        atomicAdd(&g_cnt_out[src[e]], 1);
        atomicAdd(&g_cnt_in [dst[e]], 1);
    }
}

__global__ void scanA_kernel() {
    __shared__ int sh[256];
    int i = blockIdx.x * 256 + threadIdx.x;
    int v = (i < NN) ? g_cnt_in[i] : 0;
    sh[threadIdx.x] = v;
    __syncthreads();
    for (int off = 128; off > 0; off >>= 1) {
        if (threadIdx.x < off) sh[threadIdx.x] += sh[threadIdx.x + off];
        __syncthreads();
    }
    if (threadIdx.x == 0) g_bsum[blockIdx.x] = sh[0];
}

// merged scanB+scanC: each block reduces bsum[0..b) itself, then local scan
__global__ void scanBC_kernel() {
    __shared__ int sh[256];
    __shared__ int s_pref;
    int b = blockIdx.x;
    int i = b * 256 + threadIdx.x;

    int part = 0;
    for (int j = threadIdx.x; j < b; j += 256) part += g_bsum[j];
    sh[threadIdx.x] = part;
    __syncthreads();
    for (int off = 128; off > 0; off >>= 1) {
        if (threadIdx.x < off) sh[threadIdx.x] += sh[threadIdx.x + off];
        __syncthreads();
    }
    if (threadIdx.x == 0) s_pref = sh[0];
    __syncthreads();
    int boff = s_pref;
    __syncthreads();

    int v = (i < NN) ? g_cnt_in[i] : 0;
    sh[threadIdx.x] = v;
    __syncthreads();
    for (int off = 1; off < 256; off <<= 1) {
        int x = (threadIdx.x >= off) ? sh[threadIdx.x - off] : 0;
        __syncthreads();
        sh[threadIdx.x] += x;
        __syncthreads();
    }
    if (i < NN) {
        int incl = boff + sh[threadIdx.x];
        g_row_ptr[i + 1] = incl;
        g_cursor[i] = incl - v;
        int ci = v; if (ci < 1) ci = 1;
        int co = g_cnt_out[i]; if (co < 1) co = 1;
        g_rs_in [i] = rsqrtf((float)ci);
        g_rs_out[i] = rsqrtf((float)co);
        g_sq_out[i] = sqrtf((float)co);
        if (i == 0) g_row_ptr[0] = 0;
    }
}

__global__ void scatter_edges_kernel(const int* __restrict__ src, const int* __restrict__ dst) {
    int e = blockIdx.x * blockDim.x + threadIdx.x;
    if (e < EE) {
        int pos = atomicAdd(&g_cursor[dst[e]], 1);
        g_col[pos] = src[e];
    }
}

// ================= bf16 split helpers =======================================
__device__ __forceinline__ void split_bf(float v, unsigned& h, unsigned& l) {
    __nv_bfloat16 hb = __float2bfloat16(v);
    float r = v - __bfloat162float(hb);
    __nv_bfloat16 lb = __float2bfloat16(r);
    h = (unsigned)__bfloat16_as_ushort(hb);
    l = (unsigned)__bfloat16_as_ushort(lb);
}
__device__ __forceinline__ void split4(float4 v, uint2& hi, uint2& lo) {
    unsigned h0, h1, h2, h3, l0, l1, l2, l3;
    split_bf(v.x, h0, l0);
    split_bf(v.y, h1, l1);
    split_bf(v.z, h2, l2);
    split_bf(v.w, h3, l3);
    hi.x = h0 | (h1 << 16); hi.y = h2 | (h3 << 16);
    lo.x = l0 | (l1 << 16); lo.y = l2 | (l3 << 16);
}

// precompute padded bf16 hi/lo weight tiles (one block per weight matrix)
__global__ void prep_w_kernel(const float* __restrict__ w1, const float* __restrict__ w2,
                              const float* __restrict__ pw1, const float* __restrict__ pw2) {
    const float* W = (blockIdx.x == 0) ? w1 : (blockIdx.x == 1) ? w2
                   : (blockIdx.x == 2) ? pw1 : pw2;
    char* hiB = &g_wt[blockIdx.x][0][0];
    char* loB = &g_wt[blockIdx.x][1][0];
    int tid = threadIdx.x;
#pragma unroll
    for (int it = 0; it < 16; it++) {
        int idx4 = tid + it * 256;
        int k  = idx4 >> 5;
        int c4 = idx4 & 31;
        float4 v = *(const float4*)(W + (size_t)k * 128 + c4 * 4);
        uint2 hi, lo;
        split4(v, hi, lo);
        *(uint2*)(hiB + k * ROWP + c4 * 8) = hi;
        *(uint2*)(loB + k * ROWP + c4 * 8) = lo;
    }
}

// ================= graph conv (fp16 features; R12 shape, 16-wide batch) =====
__device__ __forceinline__ void acc_edge_s(float4& acc, const __half* __restrict__ hin,
                                           int s, int lane) {
    float m = g_rs_out[s];
    uint2 rv = *(const uint2*)(hin + (size_t)s * D + lane * 4);
    float2 f0 = __half22float2(*reinterpret_cast<__half2*>(&rv.x));
    float2 f1 = __half22float2(*reinterpret_cast<__half2*>(&rv.y));
    acc.x = fmaf(m, f0.x, acc.x);
    acc.y = fmaf(m, f0.y, acc.y);
    acc.z = fmaf(m, f1.x, acc.z);
    acc.w = fmaf(m, f1.y, acc.w);
}
__device__ __forceinline__ void acc_edge_p(float4& acc, const __half* __restrict__ hin,
                                           int s, int lane) {
    uint2 rv = *(const uint2*)(hin + (size_t)s * D + lane * 4);
    float2 f0 = __half22float2(*reinterpret_cast<__half2*>(&rv.x));
    float2 f1 = __half22float2(*reinterpret_cast<__half2*>(&rv.y));
    acc.x += f0.x; acc.y += f0.y; acc.z += f1.x; acc.w += f1.y;
}

template <int SCALED>
__device__ __forceinline__ float4 gather_row(const __half* __restrict__ hin,
                                             int w, int lane) {
    int beg = g_row_ptr[w];
    int end = g_row_ptr[w + 1];
    float4 acc = make_float4(0.f, 0.f, 0.f, 0.f);
    int e = beg;
    // 16-wide batch (covers the mean degree in one pass)
    for (; e + 16 <= end; e += 16) {
        int s[16];
#pragma unroll
        for (int j = 0; j < 16; j++) s[j] = g_col[e + j];
#pragma unroll
        for (int j = 0; j < 16; j++) {
            if (SCALED) acc_edge_s(acc, hin, s[j], lane);
            else        acc_edge_p(acc, hin, s[j], lane);
        }
    }
    for (; e + 8 <= end; e += 8) {
        int s[8];
#pragma unroll
        for (int j = 0; j < 8; j++) s[j] = g_col[e + j];
#pragma unroll
        for (int j = 0; j < 8; j++) {
            if (SCALED) acc_edge_s(acc, hin, s[j], lane);
            else        acc_edge_p(acc, hin, s[j], lane);
        }
    }
    for (; e + 4 <= end; e += 4) {
        int s[4];
#pragma unroll
        for (int j = 0; j < 4; j++) s[j] = g_col[e + j];
#pragma unroll
        for (int j = 0; j < 4; j++) {
            if (SCALED) acc_edge_s(acc, hin, s[j], lane);
            else        acc_edge_p(acc, hin, s[j], lane);
        }
    }
    for (; e < end; e++) {
        if (SCALED) acc_edge_s(acc, hin, g_col[e], lane);
        else        acc_edge_p(acc, hin, g_col[e], lane);
    }
    return acc;
}

template <int SCALED>
__global__ void aggregate_mid_kernel(const __half* __restrict__ hin,
                                     __half* __restrict__ hout) {
    int w    = (blockIdx.x * blockDim.x + threadIdx.x) >> 5;
    int lane = threadIdx.x & 31;
    if (w >= NN) return;
    float4 acc = gather_row<SCALED>(hin, w, lane);
    float sc = g_rs_in[w] * g_rs_out[w];
    __half2 o0 = __floats2half2_rn(sc * acc.x, sc * acc.y);
    __half2 o1 = __floats2half2_rn(sc * acc.z, sc * acc.w);
    uint2 ov;
    ov.x = *reinterpret_cast<uint32_t*>(&o0);
    ov.y = *reinterpret_cast<uint32_t*>(&o1);
    *(uint2*)(hout + (size_t)w * D + lane * 4) = ov;
}

// last layer: rep16 = fp16( rep_fp32 + g1*h1 + g2*h2 + g3*rs_in*sum )
__global__ void aggregate_last_kernel(const __half* __restrict__ h2p,
                                      const __half* __restrict__ h1p,
                                      const float* __restrict__ gamma,
                                      const float* __restrict__ rep,
                                      __half* __restrict__ rep16) {
    int w    = (blockIdx.x * blockDim.x + threadIdx.x) >> 5;
    int lane = threadIdx.x & 31;
    if (w >= NN) return;
    float4 acc = gather_row<0>(h2p, w, lane);
    float rin = g_rs_in[w];
    float sqo = g_sq_out[w];
    float c1 = gamma[1] * sqo, c2 = gamma[2] * sqo, c3 = gamma[3] * rin;
    size_t off = (size_t)w * D + lane * 4;

    uint2 r1 = *(const uint2*)(h1p + off);
    uint2 r2 = *(const uint2*)(h2p + off);
    float2 a1 = __half22float2(*reinterpret_cast<__half2*>(&r1.x));
    float2 b1v = __half22float2(*reinterpret_cast<__half2*>(&r1.y));
    float2 a2 = __half22float2(*reinterpret_cast<__half2*>(&r2.x));
    float2 b2v = __half22float2(*reinterpret_cast<__half2*>(&r2.y));

    float4 rp = __ldcs((const float4*)(rep + off));   // streaming read
    rp.x += c1 * a1.x + c2 * a2.x + c3 * acc.x;
    rp.y += c1 * a1.y + c2 * a2.y + c3 * acc.y;
    rp.z += c1 * b1v.x + c2 * b2v.x + c3 * acc.z;
    rp.w += c1 * b1v.y + c2 * b2v.y + c3 * acc.w;

    __half2 o0 = __floats2half2_rn(rp.x, rp.y);
    __half2 o1 = __floats2half2_rn(rp.z, rp.w);
    uint2 ov;
    ov.x = *reinterpret_cast<uint32_t*>(&o0);
    ov.y = *reinterpret_cast<uint32_t*>(&o1);
    *(uint2*)(rep16 + off) = ov;
}

// ================= mma.sync plumbing (virtual-arch-safe PTX) ================
__device__ __forceinline__ uint32_t smem_u32(const void* p) {
    uint32_t a;
    asm("{ .reg .u64 t; cvta.to.shared.u64 t, %1; cvt.u32.u64 %0, t; }" : "=r"(a) : "l"(p));
    return a;
}

#define LDSM_X4(R, A)                                                        \
    asm volatile("ldmatrix.sync.aligned.m8n8.x4.shared.b16 {%0,%1,%2,%3}, [%4];" \
        : "=r"((R)[0]), "=r"((R)[1]), "=r"((R)[2]), "=r"((R)[3]) : "r"(A))

#define LDSM_X4T(R, A)                                                       \
    asm volatile("ldmatrix.sync.aligned.m8n8.x4.trans.shared.b16 {%0,%1,%2,%3}, [%4];" \
        : "=r"((R)[0]), "=r"((R)[1]), "=r"((R)[2]), "=r"((R)[3]) : "r"(A))

#define MMA16816(C, AR, B0, B1)                                              \
    asm volatile("mma.sync.aligned.m16n8k16.row.col.f32.bf16.bf16.f32 "      \
        "{%0,%1,%2,%3}, {%4,%5,%6,%7}, {%8,%9}, {%0,%1,%2,%3};"              \
        : "+f"((C)[0]), "+f"((C)[1]), "+f"((C)[2]), "+f"((C)[3])             \
        : "r"((AR)[0]), "r"((AR)[1]), "r"((AR)[2]), "r"((AR)[3]),            \
          "r"(B0), "r"(B1))

// copy precomputed hi+lo weight tile (69632 B contiguous) into smem
__device__ __forceinline__ void load_W(char* sm, int widx, int tid) {
    const uint4* src = (const uint4*)&g_wt[widx][0][0];
    uint4* dst = (uint4*)(sm + WH_OFF);
#pragma unroll
    for (int i = 0; i < 17; i++)
        dst[tid + i * 256] = src[tid + i * 256];
}

// 64x128 GEMM core: warp tile 16x64; 3-pass bf16 split
__device__ __forceinline__ void gemm_core(uint32_t sb, float acc[8][4],
                                          int wm, int wn, int lane) {
#pragma unroll
    for (int i = 0; i < 8; i++)
#pragma unroll
        for (int j = 0; j < 4; j++) acc[i][j] = 0.f;

    const uint32_t a_addr = sb + AH_OFF + (uint32_t)(wm + (lane & 15)) * ROWP
                            + ((lane >> 4) << 4);
    const uint32_t b_row  = (uint32_t)(lane & 15) * ROWP;
    const uint32_t b_col  = (uint32_t)wn * 2 + ((lane >> 4) << 4);

#pragma unroll
    for (int ks = 0; ks < 8; ks++) {
        uint32_t ah[4], al[4];
        LDSM_X4(ah, a_addr + ks * 32);
        LDSM_X4(al, a_addr + ks * 32 + (AL_OFF - AH_OFF));
        uint32_t bbase = sb + WH_OFF + (uint32_t)(ks * 16) * ROWP + b_row + b_col;
#pragma unroll
        for (int g = 0; g < 4; g++) {
            uint32_t bh[4], bl[4];
            uint32_t ba = bbase + g * 32;
            LDSM_X4T(bh, ba);
            LDSM_X4T(bl, ba + (WL_OFF - WH_OFF));
            MMA16816(acc[2 * g],     ah, bh[0], bh[1]);
            MMA16816(acc[2 * g + 1], ah, bh[2], bh[3]);
            MMA16816(acc[2 * g],     ah, bl[0], bl[1]);
            MMA16816(acc[2 * g + 1], ah, bl[2], bl[3]);
            MMA16816(acc[2 * g],     al, bh[0], bh[1]);
            MMA16816(acc[2 * g + 1], al, bh[2], bh[3]);
        }
    }
}

// relu(acc + bias) -> back into A smem tiles (bf16 hi/lo)
__device__ __forceinline__ void epi_to_A(char* sm, float acc[8][4],
                                         const float* __restrict__ bias,
                                         int wm, int wn, int lane) {
    int r0 = wm + (lane >> 2);
    int r1 = r0 + 8;
#pragma unroll
    for (int nt = 0; nt < 8; nt++) {
        int c = wn + nt * 8 + 2 * (lane & 3);
        float2 bv = *(const float2*)(bias + c);
        float v0 = fmaxf(acc[nt][0] + bv.x, 0.f);
        float v1 = fmaxf(acc[nt][1] + bv.y, 0.f);
        float v2 = fmaxf(acc[nt][2] + bv.x, 0.f);
        float v3 = fmaxf(acc[nt][3] + bv.y, 0.f);
        unsigned h0, h1, h2, h3, l0, l1, l2, l3;
        split_bf(v0, h0, l0); split_bf(v1, h1, l1);
        split_bf(v2, h2, l2); split_bf(v3, h3, l3);
        *(uint32_t*)(sm + AH_OFF + r0 * ROWP + c * 2) = h0 | (h1 << 16);
        *(uint32_t*)(sm + AL_OFF + r0 * ROWP + c * 2) = l0 | (l1 << 16);
        *(uint32_t*)(sm + AH_OFF + r1 * ROWP + c * 2) = h2 | (h3 << 16);
        *(uint32_t*)(sm + AL_OFF + r1 * ROWP + c * 2) = l2 | (l3 << 16);
    }
}

// ================= fused node MLP (mma.sync) ================================
__global__ __launch_bounds__(256) void mlp_mma_kernel(
        const float* __restrict__ x,
        const float* __restrict__ b1, const float* __restrict__ b2,
        const float* __restrict__ gam,
        __half* __restrict__ hs16, float* __restrict__ rep) {
    extern __shared__ char sm[];
    const uint32_t sb = smem_u32(sm);
    const int tid  = threadIdx.x;
    const int wid  = tid >> 5;
    const int lane = tid & 31;
    const int wm   = (wid & 3) * 16;
    const int wn   = (wid >> 2) * 64;
    const int blockRow = blockIdx.x * 64;

#pragma unroll
    for (int it = 0; it < 8; it++) {
        int idx4 = tid + it * 256;
        int r  = idx4 >> 5;
        int c4 = idx4 & 31;
        float4 v = make_float4(0.f, 0.f, 0.f, 0.f);
        if (blockRow + r < NN)
            v = *(const float4*)(x + (size_t)(blockRow + r) * D + c4 * 4);
        uint2 hi, lo;
        split4(v, hi, lo);
        *(uint2*)(sm + AH_OFF + r * ROWP + c4 * 8) = hi;
        *(uint2*)(sm + AL_OFF + r * ROWP + c4 * 8) = lo;
    }
    load_W(sm, 0, tid);
    __syncthreads();

    float acc[8][4];
    gemm_core(sb, acc, wm, wn, lane);
    __syncthreads();

    epi_to_A(sm, acc, b1, wm, wn, lane);
    load_W(sm, 1, tid);
    __syncthreads();

    gemm_core(sb, acc, wm, wn, lane);

    {
        float g0 = gam[0];
        int r0 = blockRow + wm + (lane >> 2);
        int r1 = r0 + 8;
        bool ok0 = (r0 < NN), ok1 = (r1 < NN);
#pragma unroll
        for (int nt = 0; nt < 8; nt++) {
            int c = wn + nt * 8 + 2 * (lane & 3);
            float2 bv = *(const float2*)(b2 + c);
            if (ok0) {
                float h0 = acc[nt][0] + bv.x;
                float h1 = acc[nt][1] + bv.y;
                __stcs((float2*)(rep + (size_t)r0 * D + c), make_float2(g0 * h0, g0 * h1));
                __half2 hh = __floats2half2_rn(h0, h1);
                *(uint32_t*)(hs16 + (size_t)r0 * D + c) = *reinterpret_cast<uint32_t*>(&hh);
            }
            if (ok1) {
                float h2 = acc[nt][2] + bv.x;
                float h3 = acc[nt][3] + bv.y;
                __stcs((float2*)(rep + (size_t)r1 * D + c), make_float2(g0 * h2, g0 * h3));
                __half2 hh = __floats2half2_rn(h2, h3);
                *(uint32_t*)(hs16 + (size_t)r1 * D + c) = *reinterpret_cast<uint32_t*>(&hh);
            }
        }
    }
}

// ================= fused predictor (mma.sync, fp16 rep) =====================
__global__ __launch_bounds__(256) void pred_mma_kernel(
        const int* __restrict__ ps, const int* __restrict__ pd,
        const int* __restrict__ ns, const int* __restrict__ nd,
        const float* __restrict__ b1, const float* __restrict__ b2,
        const float* __restrict__ w3, const float* __restrict__ b3,
        const __half* __restrict__ rep16, float* __restrict__ out) {
    extern __shared__ char sm[];
    const uint32_t sb = smem_u32(sm);
    const int tid  = threadIdx.x;
    const int wid  = tid >> 5;
    const int lane = tid & 31;
    const int wm   = (wid & 3) * 16;
    const int wn   = (wid >> 2) * 64;
    const int base = blockIdx.x * 64;

    int* sidx = (int*)(sm + SIDX_OFF);
    int* didx = (int*)(sm + DIDX_OFF);
    float* part = (float*)(sm + PART_OFF);

    if (tid < 64) {
        int w = base + tid;
        int s, d;
        if (w < PP) { s = ps[w]; d = pd[w]; }
        else        { s = ns[w - PP]; d = nd[w - PP]; }
        sidx[tid] = s; didx[tid] = d;
    }
    __syncthreads();

    // stage E = rep16[s]*rep16[d] (fp16 gathers -> fp32 products -> hi/lo split)
#pragma unroll
    for (int it = 0; it < 8; it++) {
        int idx4 = tid + it * 256;
        int r  = idx4 >> 5;
        int c4 = idx4 & 31;
        uint2 ra = *(const uint2*)(rep16 + (size_t)sidx[r] * D + c4 * 4);
        uint2 rb = *(const uint2*)(rep16 + (size_t)didx[r] * D + c4 * 4);
        float2 a0 = __half22float2(*reinterpret_cast<__half2*>(&ra.x));
        float2 a1 = __half22float2(*reinterpret_cast<__half2*>(&ra.y));
        float2 b0 = __half22float2(*reinterpret_cast<__half2*>(&rb.x));
        float2 b1h = __half22float2(*reinterpret_cast<__half2*>(&rb.y));
        float4 v;
        v.x = a0.x * b0.x; v.y = a0.y * b0.y;
        v.z = a1.x * b1h.x; v.w = a1.y * b1h.y;
        uint2 hi, lo;
        split4(v, hi, lo);
        *(uint2*)(sm + AH_OFF + r * ROWP + c4 * 8) = hi;
        *(uint2*)(sm + AL_OFF + r * ROWP + c4 * 8) = lo;
    }
    load_W(sm, 2, tid);
    __syncthreads();

    float acc[8][4];
    gemm_core(sb, acc, wm, wn, lane);
    __syncthreads();

    epi_to_A(sm, acc, b1, wm, wn, lane);
    load_W(sm, 3, tid);
    __syncthreads();

    gemm_core(sb, acc, wm, wn, lane);

    {
        float p0 = 0.f, p1 = 0.f;
#pragma unroll
        for (int nt = 0; nt < 8; nt++) {
            int c = wn + nt * 8 + 2 * (lane & 3);
            float2 bv = *(const float2*)(b2 + c);
            float2 wv = *(const float2*)(w3 + c);
            p0 += fmaxf(acc[nt][0] + bv.x, 0.f) * wv.x
                + fmaxf(acc[nt][1] + bv.y, 0.f) * wv.y;
            p1 += fmaxf(acc[nt][2] + bv.x, 0.f) * wv.x
                + fmaxf(acc[nt][3] + bv.y, 0.f) * wv.y;
        }
        p0 += __shfl_xor_sync(0xFFFFFFFFu, p0, 1);
        p0 += __shfl_xor_sync(0xFFFFFFFFu, p0, 2);
        p1 += __shfl_xor_sync(0xFFFFFFFFu, p1, 1);
        p1 += __shfl_xor_sync(0xFFFFFFFFu, p1, 2);
        if ((lane & 3) == 0) {
            int g = (wn >> 6);
            int rl = wm + (lane >> 2);
            part[g * 64 + rl]     = p0;
            part[g * 64 + rl + 8] = p1;
        }
    }
    __syncthreads();
    if (tid < 64) {
        out[base + tid] = part[tid] + part[64 + tid] + b3[0];
    }
}

// ================= launch ===================================================
extern "C" void kernel_launch(void* const* d_in, const int* in_sizes, int n_in,
                              void* d_out, int out_size) {
    const float* x   = (const float*)d_in[0];
    const float* w1  = (const float*)d_in[1];
    const float* b1  = (const float*)d_in[2];
    const float* w2  = (const float*)d_in[3];
    const float* b2  = (const float*)d_in[4];
    const float* gam = (const float*)d_in[5];
    const float* pw1 = (const float*)d_in[6];
    const float* pb1 = (const float*)d_in[7];
    const float* pw2 = (const float*)d_in[8];
    const float* pb2 = (const float*)d_in[9];
    const float* pw3 = (const float*)d_in[10];
    const float* pb3 = (const float*)d_in[11];
    const int* src = (const int*)d_in[12];
    const int* dst = (const int*)d_in[13];
    const int* ps  = (const int*)d_in[14];
    const int* pd  = (const int*)d_in[15];
    const int* ns  = (const int*)d_in[16];
    const int* nd  = (const int*)d_in[17];
    float* out = (float*)d_out;

    void *v0, *v1, *v2, *vrep, *vrep16;
    cudaGetSymbolAddress(&v0,     g_h0);
    cudaGetSymbolAddress(&v1,     g_h1);
    cudaGetSymbolAddress(&v2,     g_h2);
    cudaGetSymbolAddress(&vrep,   g_rep);
    cudaGetSymbolAddress(&vrep16, g_rep16);
    __half* h0 = (__half*)v0;
    __half* h1 = (__half*)v1;
    __half* h2 = (__half*)v2;
    float*  rep   = (float*)vrep;
    __half* rep16 = (__half*)vrep16;

    cudaFuncSetAttribute(mlp_mma_kernel,  cudaFuncAttributeMaxDynamicSharedMemorySize, SMEM_TOT);
    cudaFuncSetAttribute(pred_mma_kernel, cudaFuncAttributeMaxDynamicSharedMemorySize, SMEM_TOT);

    // ---- fork: CSR setup on side stream, weights+MLP on origin stream ----
    cudaStream_t s1 = 0;
    cudaEvent_t eF = 0, eJ = 0;
    bool fork_ok =
        cudaStreamCreateWithFlags(&s1, cudaStreamNonBlocking) == cudaSuccess &&
        cudaEventCreateWithFlags(&eF, cudaEventDisableTiming) == cudaSuccess &&
        cudaEventCreateWithFlags(&eJ, cudaEventDisableTiming) == cudaSuccess;
    if (fork_ok)
        fork_ok = (cudaEventRecord(eF, 0) == cudaSuccess) &&
                  (cudaStreamWaitEvent(s1, eF, 0) == cudaSuccess);
    cudaStream_t ss = fork_ok ? s1 : (cudaStream_t)0;

    const int TB = 256;
    zero_cnt_kernel<<<NB, TB, 0, ss>>>();
    count_deg_kernel<<<(EE + TB - 1) / TB, TB, 0, ss>>>(src, dst);
    scanA_kernel<<<NB, TB, 0, ss>>>();
    scanBC_kernel<<<NB, TB, 0, ss>>>();
    scatter_edges_kernel<<<(EE + TB - 1) / TB, TB, 0, ss>>>(src, dst);
    if (fork_ok) cudaEventRecord(eJ, s1);

    prep_w_kernel<<<4, 256>>>(w1, w2, pw1, pw2);
    mlp_mma_kernel<<<(NN + 63) / 64, TB, SMEM_TOT>>>(x, b1, b2, gam, h0, rep);

    if (fork_ok) cudaStreamWaitEvent((cudaStream_t)0, eJ, 0);

    aggregate_mid_kernel<1><<<(NN * 32 + TB - 1) / TB, TB>>>(h0, h1);
    aggregate_mid_kernel<0><<<(NN * 32 + TB - 1) / TB, TB>>>(h1, h2);
    aggregate_last_kernel<<<(NN * 32 + TB - 1) / TB, TB>>>(h2, h1, gam, rep, rep16);

    pred_mma_kernel<<<(2 * PP) / 64, TB, SMEM_TOT>>>(
        ps, pd, ns, nd, pb1, pb2, pw3, pb3, rep16, out);
}

// round 17
// speedup vs baseline: 1.0734x; 1.0369x over previous
#include <cuda_runtime.h>
#include <cuda_bf16.h>
#include <cuda_fp16.h>
#include <cstdint>

#define NN 100000
#define EE 1600000
#define PP 100000
#define D  128
#define NB 391   // ceil(NN/256)

// ---- smem layout (bytes) ----
#define ROWP     272            // 136 bf16 per row (128 used + pad)
#define AH_OFF   0              // A hi : 64 x ROWP
#define AL_OFF   17408
#define WH_OFF   34816          // W hi : 128 x ROWP
#define WL_OFF   69632          // contiguous after WH
#define SIDX_OFF 104448
#define DIDX_OFF 104704
#define PART_OFF 104960         // 2 x 64 floats
#define SMEM_TOT 105472

#define WTILE_B  34816          // 128 * ROWP

// ================= scratch (device globals; no allocation) =================
__device__ __align__(128) __half g_h0   [(size_t)NN * D];
__device__ __align__(128) __half g_h1   [(size_t)NN * D];
__device__ __align__(128) __half g_h2   [(size_t)NN * D];
__device__ __align__(128) __half g_rep16[(size_t)NN * D];
__device__ __align__(16)  char   g_wt   [4][2][WTILE_B];  // w1,w2,pw1,pw2 hi/lo
__device__ int   g_cnt_in [NN];
__device__ int   g_cnt_out[NN];
__device__ float g_rs_in  [NN];
__device__ float g_rs_out [NN];
__device__ float g_sq_out [NN];
__device__ int   g_row_ptr[NN + 1];
__device__ int   g_cursor [NN];
__device__ int   g_col    [EE];
__device__ int   g_bsum   [NB];

// ================= graph structure ==========================================
__global__ void zero_cnt_kernel() {
    int v = blockIdx.x * blockDim.x + threadIdx.x;
    if (v < NN) { g_cnt_in[v] = 0; g_cnt_out[v] = 0; }
}

__global__ void count_deg_kernel(const int* __restrict__ src, const int* __restrict__ dst) {
    int e = blockIdx.x * blockDim.x + threadIdx.x;
    if (e < EE) {
        atomicAdd(&g_cnt_out[src[e]], 1);
        atomicAdd(&g_cnt_in [dst[e]], 1);
    }
}

__global__ void scanA_kernel() {
    __shared__ int sh[256];
    int i = blockIdx.x * 256 + threadIdx.x;
    int v = (i < NN) ? g_cnt_in[i] : 0;
    sh[threadIdx.x] = v;
    __syncthreads();
    for (int off = 128; off > 0; off >>= 1) {
        if (threadIdx.x < off) sh[threadIdx.x] += sh[threadIdx.x + off];
        __syncthreads();
    }
    if (threadIdx.x == 0) g_bsum[blockIdx.x] = sh[0];
}

// merged scanB+scanC: each block reduces bsum[0..b) itself, then local scan
__global__ void scanBC_kernel() {
    __shared__ int sh[256];
    __shared__ int s_pref;
    int b = blockIdx.x;
    int i = b * 256 + threadIdx.x;

    int part = 0;
    for (int j = threadIdx.x; j < b; j += 256) part += g_bsum[j];
    sh[threadIdx.x] = part;
    __syncthreads();
    for (int off = 128; off > 0; off >>= 1) {
        if (threadIdx.x < off) sh[threadIdx.x] += sh[threadIdx.x + off];
        __syncthreads();
    }
    if (threadIdx.x == 0) s_pref = sh[0];
    __syncthreads();
    int boff = s_pref;
    __syncthreads();

    int v = (i < NN) ? g_cnt_in[i] : 0;
    sh[threadIdx.x] = v;
    __syncthreads();
    for (int off = 1; off < 256; off <<= 1) {
        int x = (threadIdx.x >= off) ? sh[threadIdx.x - off] : 0;
        __syncthreads();
        sh[threadIdx.x] += x;
        __syncthreads();
    }
    if (i < NN) {
        int incl = boff + sh[threadIdx.x];
        g_row_ptr[i + 1] = incl;
        g_cursor[i] = incl - v;
        int ci = v; if (ci < 1) ci = 1;
        int co = g_cnt_out[i]; if (co < 1) co = 1;
        g_rs_in [i] = rsqrtf((float)ci);
        g_rs_out[i] = rsqrtf((float)co);
        g_sq_out[i] = sqrtf((float)co);
        if (i == 0) g_row_ptr[0] = 0;
    }
}

__global__ void scatter_edges_kernel(const int* __restrict__ src, const int* __restrict__ dst) {
    int e = blockIdx.x * blockDim.x + threadIdx.x;
    if (e < EE) {
        int pos = atomicAdd(&g_cursor[dst[e]], 1);
        g_col[pos] = src[e];
    }
}

// ================= bf16 split helpers =======================================
__device__ __forceinline__ void split_bf(float v, unsigned& h, unsigned& l) {
    __nv_bfloat16 hb = __float2bfloat16(v);
    float r = v - __bfloat162float(hb);
    __nv_bfloat16 lb = __float2bfloat16(r);
    h = (unsigned)__bfloat16_as_ushort(hb);
    l = (unsigned)__bfloat16_as_ushort(lb);
}
__device__ __forceinline__ void split4(float4 v, uint2& hi, uint2& lo) {
    unsigned h0, h1, h2, h3, l0, l1, l2, l3;
    split_bf(v.x, h0, l0);
    split_bf(v.y, h1, l1);
    split_bf(v.z, h2, l2);
    split_bf(v.w, h3, l3);
    hi.x = h0 | (h1 << 16); hi.y = h2 | (h3 << 16);
    lo.x = l0 | (l1 << 16); lo.y = l2 | (l3 << 16);
}

// precompute padded bf16 hi/lo weight tiles (one block per weight matrix)
__global__ void prep_w_kernel(const float* __restrict__ w1, const float* __restrict__ w2,
                              const float* __restrict__ pw1, const float* __restrict__ pw2) {
    const float* W = (blockIdx.x == 0) ? w1 : (blockIdx.x == 1) ? w2
                   : (blockIdx.x == 2) ? pw1 : pw2;
    char* hiB = &g_wt[blockIdx.x][0][0];
    char* loB = &g_wt[blockIdx.x][1][0];
    int tid = threadIdx.x;
#pragma unroll
    for (int it = 0; it < 16; it++) {
        int idx4 = tid + it * 256;
        int k  = idx4 >> 5;
        int c4 = idx4 & 31;
        float4 v = *(const float4*)(W + (size_t)k * 128 + c4 * 4);
        uint2 hi, lo;
        split4(v, hi, lo);
        *(uint2*)(hiB + k * ROWP + c4 * 8) = hi;
        *(uint2*)(loB + k * ROWP + c4 * 8) = lo;
    }
}

// ================= graph conv (fp16 features; R12 gather shape) =============
__device__ __forceinline__ void acc_edge_s(float4& acc, const __half* __restrict__ hin,
                                           int s, int lane) {
    float m = g_rs_out[s];
    uint2 rv = *(const uint2*)(hin + (size_t)s * D + lane * 4);
    float2 f0 = __half22float2(*reinterpret_cast<__half2*>(&rv.x));
    float2 f1 = __half22float2(*reinterpret_cast<__half2*>(&rv.y));
    acc.x = fmaf(m, f0.x, acc.x);
    acc.y = fmaf(m, f0.y, acc.y);
    acc.z = fmaf(m, f1.x, acc.z);
    acc.w = fmaf(m, f1.y, acc.w);
}
__device__ __forceinline__ void acc_edge_p(float4& acc, const __half* __restrict__ hin,
                                           int s, int lane) {
    uint2 rv = *(const uint2*)(hin + (size_t)s * D + lane * 4);
    float2 f0 = __half22float2(*reinterpret_cast<__half2*>(&rv.x));
    float2 f1 = __half22float2(*reinterpret_cast<__half2*>(&rv.y));
    acc.x += f0.x; acc.y += f0.y; acc.z += f1.x; acc.w += f1.y;
}

template <int SCALED>
__device__ __forceinline__ float4 gather_row(const __half* __restrict__ hin,
                                             int w, int lane) {
    int beg = g_row_ptr[w];
    int end = g_row_ptr[w + 1];
    float4 acc = make_float4(0.f, 0.f, 0.f, 0.f);
    int e = beg;
    for (; e + 8 <= end; e += 8) {
        int s[8];
#pragma unroll
        for (int j = 0; j < 8; j++) s[j] = g_col[e + j];
#pragma unroll
        for (int j = 0; j < 8; j++) {
            if (SCALED) acc_edge_s(acc, hin, s[j], lane);
            else        acc_edge_p(acc, hin, s[j], lane);
        }
    }
    for (; e + 4 <= end; e += 4) {
        int s[4];
#pragma unroll
        for (int j = 0; j < 4; j++) s[j] = g_col[e + j];
#pragma unroll
        for (int j = 0; j < 4; j++) {
            if (SCALED) acc_edge_s(acc, hin, s[j], lane);
            else        acc_edge_p(acc, hin, s[j], lane);
        }
    }
    for (; e < end; e++) {
        if (SCALED) acc_edge_s(acc, hin, g_col[e], lane);
        else        acc_edge_p(acc, hin, g_col[e], lane);
    }
    return acc;
}

template <int SCALED>
__global__ void aggregate_mid_kernel(const __half* __restrict__ hin,
                                     __half* __restrict__ hout) {
    int w    = (blockIdx.x * blockDim.x + threadIdx.x) >> 5;
    int lane = threadIdx.x & 31;
    if (w >= NN) return;
    float4 acc = gather_row<SCALED>(hin, w, lane);
    float sc = g_rs_in[w] * g_rs_out[w];
    __half2 o0 = __floats2half2_rn(sc * acc.x, sc * acc.y);
    __half2 o1 = __floats2half2_rn(sc * acc.z, sc * acc.w);
    uint2 ov;
    ov.x = *reinterpret_cast<uint32_t*>(&o0);
    ov.y = *reinterpret_cast<uint32_t*>(&o1);
    *(uint2*)(hout + (size_t)w * D + lane * 4) = ov;
}

// last layer: rep16 = fp16( g0*h0 + g1*h1 + g2*h2 + g3*rs_in*sum )
// h0 read from fp16 g_h0 (unscaled); h1/h2 undo the rs_out pre-scale via sq_out
__global__ void aggregate_last_kernel(const __half* __restrict__ h2p,
                                      const __half* __restrict__ h1p,
                                      const __half* __restrict__ h0p,
                                      const float* __restrict__ gamma,
                                      __half* __restrict__ rep16) {
    int w    = (blockIdx.x * blockDim.x + threadIdx.x) >> 5;
    int lane = threadIdx.x & 31;
    if (w >= NN) return;
    float4 acc = gather_row<0>(h2p, w, lane);
    float rin = g_rs_in[w];
    float sqo = g_sq_out[w];
    float c0 = gamma[0];
    float c1 = gamma[1] * sqo, c2 = gamma[2] * sqo, c3 = gamma[3] * rin;
    size_t off = (size_t)w * D + lane * 4;

    uint2 r0 = *(const uint2*)(h0p + off);
    uint2 r1 = *(const uint2*)(h1p + off);
    uint2 r2 = *(const uint2*)(h2p + off);
    float2 z0 = __half22float2(*reinterpret_cast<__half2*>(&r0.x));
    float2 z1 = __half22float2(*reinterpret_cast<__half2*>(&r0.y));
    float2 a1 = __half22float2(*reinterpret_cast<__half2*>(&r1.x));
    float2 b1v = __half22float2(*reinterpret_cast<__half2*>(&r1.y));
    float2 a2 = __half22float2(*reinterpret_cast<__half2*>(&r2.x));
    float2 b2v = __half22float2(*reinterpret_cast<__half2*>(&r2.y));

    float px = c0 * z0.x + c1 * a1.x + c2 * a2.x + c3 * acc.x;
    float py = c0 * z0.y + c1 * a1.y + c2 * a2.y + c3 * acc.y;
    float pz = c0 * z1.x + c1 * b1v.x + c2 * b2v.x + c3 * acc.z;
    float pw = c0 * z1.y + c1 * b1v.y + c2 * b2v.y + c3 * acc.w;

    __half2 o0 = __floats2half2_rn(px, py);
    __half2 o1 = __floats2half2_rn(pz, pw);
    uint2 ov;
    ov.x = *reinterpret_cast<uint32_t*>(&o0);
    ov.y = *reinterpret_cast<uint32_t*>(&o1);
    *(uint2*)(rep16 + off) = ov;
}

// ================= mma.sync plumbing (virtual-arch-safe PTX) ================
__device__ __forceinline__ uint32_t smem_u32(const void* p) {
    uint32_t a;
    asm("{ .reg .u64 t; cvta.to.shared.u64 t, %1; cvt.u32.u64 %0, t; }" : "=r"(a) : "l"(p));
    return a;
}

#define LDSM_X4(R, A)                                                        \
    asm volatile("ldmatrix.sync.aligned.m8n8.x4.shared.b16 {%0,%1,%2,%3}, [%4];" \
        : "=r"((R)[0]), "=r"((R)[1]), "=r"((R)[2]), "=r"((R)[3]) : "r"(A))

#define LDSM_X4T(R, A)                                                       \
    asm volatile("ldmatrix.sync.aligned.m8n8.x4.trans.shared.b16 {%0,%1,%2,%3}, [%4];" \
        : "=r"((R)[0]), "=r"((R)[1]), "=r"((R)[2]), "=r"((R)[3]) : "r"(A))

#define MMA16816(C, AR, B0, B1)                                              \
    asm volatile("mma.sync.aligned.m16n8k16.row.col.f32.bf16.bf16.f32 "      \
        "{%0,%1,%2,%3}, {%4,%5,%6,%7}, {%8,%9}, {%0,%1,%2,%3};"              \
        : "+f"((C)[0]), "+f"((C)[1]), "+f"((C)[2]), "+f"((C)[3])             \
        : "r"((AR)[0]), "r"((AR)[1]), "r"((AR)[2]), "r"((AR)[3]),            \
          "r"(B0), "r"(B1))

// copy precomputed hi+lo weight tile (69632 B contiguous) into smem
__device__ __forceinline__ void load_W(char* sm, int widx, int tid) {
    const uint4* src = (const uint4*)&g_wt[widx][0][0];
    uint4* dst = (uint4*)(sm + WH_OFF);
#pragma unroll
    for (int i = 0; i < 17; i++)
        dst[tid + i * 256] = src[tid + i * 256];
}

// 64x128 GEMM core: warp tile 16x64; 3-pass bf16 split
__device__ __forceinline__ void gemm_core(uint32_t sb, float acc[8][4],
                                          int wm, int wn, int lane) {
#pragma unroll
    for (int i = 0; i < 8; i++)
#pragma unroll
        for (int j = 0; j < 4; j++) acc[i][j] = 0.f;

    const uint32_t a_addr = sb + AH_OFF + (uint32_t)(wm + (lane & 15)) * ROWP
                            + ((lane >> 4) << 4);
    const uint32_t b_row  = (uint32_t)(lane & 15) * ROWP;
    const uint32_t b_col  = (uint32_t)wn * 2 + ((lane >> 4) << 4);

#pragma unroll
    for (int ks = 0; ks < 8; ks++) {
        uint32_t ah[4], al[4];
        LDSM_X4(ah, a_addr + ks * 32);
        LDSM_X4(al, a_addr + ks * 32 + (AL_OFF - AH_OFF));
        uint32_t bbase = sb + WH_OFF + (uint32_t)(ks * 16) * ROWP + b_row + b_col;
#pragma unroll
        for (int g = 0; g < 4; g++) {
            uint32_t bh[4], bl[4];
            uint32_t ba = bbase + g * 32;
            LDSM_X4T(bh, ba);
            LDSM_X4T(bl, ba + (WL_OFF - WH_OFF));
            MMA16816(acc[2 * g],     ah, bh[0], bh[1]);
            MMA16816(acc[2 * g + 1], ah, bh[2], bh[3]);
            MMA16816(acc[2 * g],     ah, bl[0], bl[1]);
            MMA16816(acc[2 * g + 1], ah, bl[2], bl[3]);
            MMA16816(acc[2 * g],     al, bh[0], bh[1]);
            MMA16816(acc[2 * g + 1], al, bh[2], bh[3]);
        }
    }
}

// relu(acc + bias) -> back into A smem tiles (bf16 hi/lo)
__device__ __forceinline__ void epi_to_A(char* sm, float acc[8][4],
                                         const float* __restrict__ bias,
                                         int wm, int wn, int lane) {
    int r0 = wm + (lane >> 2);
    int r1 = r0 + 8;
#pragma unroll
    for (int nt = 0; nt < 8; nt++) {
        int c = wn + nt * 8 + 2 * (lane & 3);
        float2 bv = *(const float2*)(bias + c);
        float v0 = fmaxf(acc[nt][0] + bv.x, 0.f);
        float v1 = fmaxf(acc[nt][1] + bv.y, 0.f);
        float v2 = fmaxf(acc[nt][2] + bv.x, 0.f);
        float v3 = fmaxf(acc[nt][3] + bv.y, 0.f);
        unsigned h0, h1, h2, h3, l0, l1, l2, l3;
        split_bf(v0, h0, l0); split_bf(v1, h1, l1);
        split_bf(v2, h2, l2); split_bf(v3, h3, l3);
        *(uint32_t*)(sm + AH_OFF + r0 * ROWP + c * 2) = h0 | (h1 << 16);
        *(uint32_t*)(sm + AL_OFF + r0 * ROWP + c * 2) = l0 | (l1 << 16);
        *(uint32_t*)(sm + AH_OFF + r1 * ROWP + c * 2) = h2 | (h3 << 16);
        *(uint32_t*)(sm + AL_OFF + r1 * ROWP + c * 2) = l2 | (l3 << 16);
    }
}

// ================= fused node MLP (mma.sync) ================================
// writes h0 (unscaled, fp16) only; the gamma0 term is folded into agg_last
__global__ __launch_bounds__(256) void mlp_mma_kernel(
        const float* __restrict__ x,
        const float* __restrict__ b1, const float* __restrict__ b2,
        __half* __restrict__ hs16) {
    extern __shared__ char sm[];
    const uint32_t sb = smem_u32(sm);
    const int tid  = threadIdx.x;
    const int wid  = tid >> 5;
    const int lane = tid & 31;
    const int wm   = (wid & 3) * 16;
    const int wn   = (wid >> 2) * 64;
    const int blockRow = blockIdx.x * 64;

#pragma unroll
    for (int it = 0; it < 8; it++) {
        int idx4 = tid + it * 256;
        int r  = idx4 >> 5;
        int c4 = idx4 & 31;
        float4 v = make_float4(0.f, 0.f, 0.f, 0.f);
        if (blockRow + r < NN)
            v = *(const float4*)(x + (size_t)(blockRow + r) * D + c4 * 4);
        uint2 hi, lo;
        split4(v, hi, lo);
        *(uint2*)(sm + AH_OFF + r * ROWP + c4 * 8) = hi;
        *(uint2*)(sm + AL_OFF + r * ROWP + c4 * 8) = lo;
    }
    load_W(sm, 0, tid);
    __syncthreads();

    float acc[8][4];
    gemm_core(sb, acc, wm, wn, lane);
    __syncthreads();

    epi_to_A(sm, acc, b1, wm, wn, lane);
    load_W(sm, 1, tid);
    __syncthreads();

    gemm_core(sb, acc, wm, wn, lane);

    {
        int r0 = blockRow + wm + (lane >> 2);
        int r1 = r0 + 8;
        bool ok0 = (r0 < NN), ok1 = (r1 < NN);
#pragma unroll
        for (int nt = 0; nt < 8; nt++) {
            int c = wn + nt * 8 + 2 * (lane & 3);
            float2 bv = *(const float2*)(b2 + c);
            if (ok0) {
                float h0 = acc[nt][0] + bv.x;
                float h1 = acc[nt][1] + bv.y;
                __half2 hh = __floats2half2_rn(h0, h1);
                *(uint32_t*)(hs16 + (size_t)r0 * D + c) = *reinterpret_cast<uint32_t*>(&hh);
            }
            if (ok1) {
                float h2 = acc[nt][2] + bv.x;
                float h3 = acc[nt][3] + bv.y;
                __half2 hh = __floats2half2_rn(h2, h3);
                *(uint32_t*)(hs16 + (size_t)r1 * D + c) = *reinterpret_cast<uint32_t*>(&hh);
            }
        }
    }
}

// ================= fused predictor (mma.sync, fp16 rep) =====================
__global__ __launch_bounds__(256) void pred_mma_kernel(
        const int* __restrict__ ps, const int* __restrict__ pd,
        const int* __restrict__ ns, const int* __restrict__ nd,
        const float* __restrict__ b1, const float* __restrict__ b2,
        const float* __restrict__ w3, const float* __restrict__ b3,
        const __half* __restrict__ rep16, float* __restrict__ out) {
    extern __shared__ char sm[];
    const uint32_t sb = smem_u32(sm);
    const int tid  = threadIdx.x;
    const int wid  = tid >> 5;
    const int lane = tid & 31;
    const int wm   = (wid & 3) * 16;
    const int wn   = (wid >> 2) * 64;
    const int base = blockIdx.x * 64;

    int* sidx = (int*)(sm + SIDX_OFF);
    int* didx = (int*)(sm + DIDX_OFF);
    float* part = (float*)(sm + PART_OFF);

    if (tid < 64) {
        int w = base + tid;
        int s, d;
        if (w < PP) { s = ps[w]; d = pd[w]; }
        else        { s = ns[w - PP]; d = nd[w - PP]; }
        sidx[tid] = s; didx[tid] = d;
    }
    __syncthreads();

    // stage E = rep16[s]*rep16[d] (fp16 gathers -> fp32 products -> hi/lo split)
#pragma unroll
    for (int it = 0; it < 8; it++) {
        int idx4 = tid + it * 256;
        int r  = idx4 >> 5;
        int c4 = idx4 & 31;
        uint2 ra = *(const uint2*)(rep16 + (size_t)sidx[r] * D + c4 * 4);
        uint2 rb = *(const uint2*)(rep16 + (size_t)didx[r] * D + c4 * 4);
        float2 a0 = __half22float2(*reinterpret_cast<__half2*>(&ra.x));
        float2 a1 = __half22float2(*reinterpret_cast<__half2*>(&ra.y));
        float2 b0 = __half22float2(*reinterpret_cast<__half2*>(&rb.x));
        float2 b1h = __half22float2(*reinterpret_cast<__half2*>(&rb.y));
        float4 v;
        v.x = a0.x * b0.x; v.y = a0.y * b0.y;
        v.z = a1.x * b1h.x; v.w = a1.y * b1h.y;
        uint2 hi, lo;
        split4(v, hi, lo);
        *(uint2*)(sm + AH_OFF + r * ROWP + c4 * 8) = hi;
        *(uint2*)(sm + AL_OFF + r * ROWP + c4 * 8) = lo;
    }
    load_W(sm, 2, tid);
    __syncthreads();

    float acc[8][4];
    gemm_core(sb, acc, wm, wn, lane);
    __syncthreads();

    epi_to_A(sm, acc, b1, wm, wn, lane);
    load_W(sm, 3, tid);
    __syncthreads();

    gemm_core(sb, acc, wm, wn, lane);

    {
        float p0 = 0.f, p1 = 0.f;
#pragma unroll
        for (int nt = 0; nt < 8; nt++) {
            int c = wn + nt * 8 + 2 * (lane & 3);
            float2 bv = *(const float2*)(b2 + c);
            float2 wv = *(const float2*)(w3 + c);
            p0 += fmaxf(acc[nt][0] + bv.x, 0.f) * wv.x
                + fmaxf(acc[nt][1] + bv.y, 0.f) * wv.y;
            p1 += fmaxf(acc[nt][2] + bv.x, 0.f) * wv.x
                + fmaxf(acc[nt][3] + bv.y, 0.f) * wv.y;
        }
        p0 += __shfl_xor_sync(0xFFFFFFFFu, p0, 1);
        p0 += __shfl_xor_sync(0xFFFFFFFFu, p0, 2);
        p1 += __shfl_xor_sync(0xFFFFFFFFu, p1, 1);
        p1 += __shfl_xor_sync(0xFFFFFFFFu, p1, 2);
        if ((lane & 3) == 0) {
            int g = (wn >> 6);
            int rl = wm + (lane >> 2);
            part[g * 64 + rl]     = p0;
            part[g * 64 + rl + 8] = p1;
        }
    }
    __syncthreads();
    if (tid < 64) {
        out[base + tid] = part[tid] + part[64 + tid] + b3[0];
    }
}

// ================= launch ===================================================
extern "C" void kernel_launch(void* const* d_in, const int* in_sizes, int n_in,
                              void* d_out, int out_size) {
    const float* x   = (const float*)d_in[0];
    const float* w1  = (const float*)d_in[1];
    const float* b1  = (const float*)d_in[2];
    const float* w2  = (const float*)d_in[3];
    const float* b2  = (const float*)d_in[4];
    const float* gam = (const float*)d_in[5];
    const float* pw1 = (const float*)d_in[6];
    const float* pb1 = (const float*)d_in[7];
    const float* pw2 = (const float*)d_in[8];
    const float* pb2 = (const float*)d_in[9];
    const float* pw3 = (const float*)d_in[10];
    const float* pb3 = (const float*)d_in[11];
    const int* src = (const int*)d_in[12];
    const int* dst = (const int*)d_in[13];
    const int* ps  = (const int*)d_in[14];
    const int* pd  = (const int*)d_in[15];
    const int* ns  = (const int*)d_in[16];
    const int* nd  = (const int*)d_in[17];
    float* out = (float*)d_out;

    void *v0, *v1, *v2, *vrep16;
    cudaGetSymbolAddress(&v0,     g_h0);
    cudaGetSymbolAddress(&v1,     g_h1);
    cudaGetSymbolAddress(&v2,     g_h2);
    cudaGetSymbolAddress(&vrep16, g_rep16);
    __half* h0 = (__half*)v0;
    __half* h1 = (__half*)v1;
    __half* h2 = (__half*)v2;
    __half* rep16 = (__half*)vrep16;

    cudaFuncSetAttribute(mlp_mma_kernel,  cudaFuncAttributeMaxDynamicSharedMemorySize, SMEM_TOT);
    cudaFuncSetAttribute(pred_mma_kernel, cudaFuncAttributeMaxDynamicSharedMemorySize, SMEM_TOT);

    // ---- fork: CSR setup on side stream, weights+MLP on origin stream ----
    cudaStream_t s1 = 0;
    cudaEvent_t eF = 0, eJ = 0;
    bool fork_ok =
        cudaStreamCreateWithFlags(&s1, cudaStreamNonBlocking) == cudaSuccess &&
        cudaEventCreateWithFlags(&eF, cudaEventDisableTiming) == cudaSuccess &&
        cudaEventCreateWithFlags(&eJ, cudaEventDisableTiming) == cudaSuccess;
    if (fork_ok)
        fork_ok = (cudaEventRecord(eF, 0) == cudaSuccess) &&
                  (cudaStreamWaitEvent(s1, eF, 0) == cudaSuccess);
    cudaStream_t ss = fork_ok ? s1 : (cudaStream_t)0;

    const int TB = 256;
    zero_cnt_kernel<<<NB, TB, 0, ss>>>();
    count_deg_kernel<<<(EE + TB - 1) / TB, TB, 0, ss>>>(src, dst);
    scanA_kernel<<<NB, TB, 0, ss>>>();
    scanBC_kernel<<<NB, TB, 0, ss>>>();
    scatter_edges_kernel<<<(EE + TB - 1) / TB, TB, 0, ss>>>(src, dst);
    if (fork_ok) cudaEventRecord(eJ, s1);

    prep_w_kernel<<<4, 256>>>(w1, w2, pw1, pw2);
    mlp_mma_kernel<<<(NN + 63) / 64, TB, SMEM_TOT>>>(x, b1, b2, h0);

    if (fork_ok) cudaStreamWaitEvent((cudaStream_t)0, eJ, 0);

    aggregate_mid_kernel<1><<<(NN * 32 + TB - 1) / TB, TB>>>(h0, h1);
    aggregate_mid_kernel<0><<<(NN * 32 + TB - 1) / TB, TB>>>(h1, h2);
    aggregate_last_kernel<<<(NN * 32 + TB - 1) / TB, TB>>>(h2, h1, h0, gam, rep16);

    pred_mma_kernel<<<(2 * PP) / 64, TB, SMEM_TOT>>>(
        ps, pd, ns, nd, pb1, pb2, pw3, pb3, rep16, out);
}